// round 4
// baseline (speedup 1.0000x reference)
#include <cuda_runtime.h>

// ---------------------------------------------------------------------------
// MixerBlock: token-mix (YAT + linear, residual) then channel-mix (YAT + linear, residual)
// Shapes: B=64, P=196, C=768, T_MLP=384, C_MLP=3072. All fp32.
// ---------------------------------------------------------------------------

#define EPSV 0.1f

// ---- scratch (device globals; no allocations allowed) ----
__device__ __align__(128) float g_H1[49152 * 384];   // (B*C, T_MLP)   75.5 MB
__device__ __align__(128) float g_X2[64 * 196 * 768]; // (B,P,C) after token mix  38.5 MB
__device__ __align__(128) float g_H3[12544 * 3072];  // (B*P, C_MLP)   154 MB
__device__ __align__(128) float g_xn1[49152];        // ||x_t||^2 per (b,c) row
__device__ __align__(128) float g_xn2[12544];        // ||X2||^2 per (b,p) row
__device__ __align__(128) float g_twn[384];          // ||tw_row||^2
__device__ __align__(128) float g_cwn[3072];         // ||cw_row||^2

// ---- packed f32x2 helpers (Blackwell FFMA2: 2x fp32 FMA throughput) ----
__device__ __forceinline__ void ffma2(unsigned long long &d,
                                      unsigned long long a,
                                      unsigned long long b) {
    asm("fma.rn.f32x2 %0, %1, %2, %0;" : "+l"(d) : "l"(a), "l"(b));
}
__device__ __forceinline__ unsigned long long pack2(float x) {
    unsigned long long r;
    unsigned u = __float_as_uint(x);
    asm("mov.b64 %0, {%1, %1};" : "=l"(r) : "r"(u));
    return r;
}

// ---------------------------------------------------------------------------
// Row-norm helper: dst[row] = sum_k src[row*K+k]^2   (warp per row)
// sel: 0 -> g_twn, 1 -> g_cwn, 2 -> g_xn2 with src = g_X2
// ---------------------------------------------------------------------------
__global__ void rownorm_kernel(const float* __restrict__ srcArg, int rows, int K, int sel) {
    const float* src = (sel == 2) ? g_X2 : srcArg;
    float* dst = (sel == 0) ? g_twn : (sel == 1) ? g_cwn : g_xn2;
    int row = blockIdx.x * 4 + (threadIdx.x >> 5);
    if (row >= rows) return;
    int lane = threadIdx.x & 31;
    const float* p = src + (long)row * K;
    float s = 0.f;
    for (int k = lane; k < K; k += 32) { float v = p[k]; s = fmaf(v, v, s); }
#pragma unroll
    for (int o = 16; o; o >>= 1) s += __shfl_xor_sync(0xffffffffu, s, o);
    if (lane == 0) dst[row] = s;
}

// x norms over the patch dim: g_xn1[b*768+c] = sum_p x[b,p,c]^2
__global__ void xnorm1_kernel(const float* __restrict__ x) {
    int g = blockIdx.x * blockDim.x + threadIdx.x;   // < 49152
    int b = g / 768, c = g - b * 768;
    const float* p = x + (long)b * 196 * 768 + c;
    float s = 0.f;
#pragma unroll 4
    for (int i = 0; i < 196; ++i) { float v = p[(long)i * 768]; s = fmaf(v, v, s); }
    g_xn1[g] = s;
}

// ---------------------------------------------------------------------------
// Fused GEMM (128x128 tile, BK=8, 256 threads, 8x8 micro-tile via f32x2).
//   C[m,n] = sum_k A[m,k] * W[n,k]          (W row-major (N,K))
// MODE 0: A = x (transposed access, m=(b,c), k=p), epilogue = token YAT -> g_H1
// MODE 1: A = g_H1, epilogue = residual + transpose -> g_X2[(b,p,c)] (n=p)
// MODE 2: A = g_X2, epilogue = channel YAT -> g_H3
// MODE 3: A = g_H3, epilogue = residual -> out (row-major)
// ---------------------------------------------------------------------------
template<int MODE>
__global__ __launch_bounds__(256, 2) void gemm_kernel(
    const float* __restrict__ Aarg,
    const float* __restrict__ W,
    const float* __restrict__ bias,
    const float* __restrict__ alpha,
    const float* __restrict__ resArg,
    float* __restrict__ outArg)
{
    constexpr int N  = (MODE == 0) ? 384 : (MODE == 1) ? 196 : (MODE == 2) ? 3072 : 768;
    constexpr int K  = (MODE == 0) ? 196 : (MODE == 1) ? 384 : (MODE == 2) ? 768 : 3072;
    constexpr int KT = (K + 7) / 8;
    constexpr bool KRAG = (K % 8) != 0;    // only MODE 0
    constexpr bool NRAG = (N % 128) != 0;  // only MODE 1

    const float* A = (MODE == 0) ? Aarg : (MODE == 1) ? g_H1 : (MODE == 2) ? g_X2 : g_H3;
    float* out = (MODE == 0) ? g_H1 : (MODE == 1) ? g_X2 : (MODE == 2) ? g_H3 : outArg;

    __shared__ float As[2][8][132];
    __shared__ float Bs[2][8][132];

    const int tid = threadIdx.x;
    const int m0 = blockIdx.y * 128;
    const int n0 = blockIdx.x * 128;

    // ---- B global-load mapping (transpose (N,K) row-major -> Bs[k][n]) ----
    const int bn  = tid >> 1;
    const int bk4 = (tid & 1) * 4;
    const int gnb = n0 + bn;
    const bool bnOK = !NRAG || (gnb < N);
    const float* Bptr = W + (long)gnb * K + bk4;

    // ---- A global-load mapping ----
    int a_kk, a_mm;
    const float* Aptr;
    if (MODE == 0) {
        a_kk = tid >> 5;              // 0..7
        a_mm = (tid & 31) * 4;        // 0..124
        const int b = m0 / 768;
        const int c = (m0 % 768) + a_mm;
        Aptr = A + ((long)(b * 196 + a_kk)) * 768 + c;   // advance by 8*768 per kt
    } else {
        a_mm = tid >> 1;              // 0..127
        a_kk = (tid & 1) * 4;         // 0 or 4
        Aptr = A + (long)(m0 + a_mm) * K + a_kk;          // advance by 8 per kt
    }

    const int tx = tid & 15;
    const int ty = tid >> 4;

    unsigned long long acc[8][4];
#pragma unroll
    for (int i = 0; i < 8; ++i)
#pragma unroll
        for (int j = 0; j < 4; ++j) acc[i][j] = 0ull;

    auto ldA = [&](int kt) -> float4 {
        if (MODE == 0) {
            if (!KRAG || (kt * 8 + a_kk) < K)
                return *(const float4*)(Aptr + (long)kt * 8 * 768);
            return make_float4(0.f, 0.f, 0.f, 0.f);
        } else {
            return *(const float4*)(Aptr + kt * 8);
        }
    };
    auto ldB = [&](int kt) -> float4 {
        bool ok = bnOK && (!KRAG || (kt * 8 + bk4) < K);
        if (ok) return *(const float4*)(Bptr + kt * 8);
        return make_float4(0.f, 0.f, 0.f, 0.f);
    };
    auto stA = [&](int bu, float4 v) {
        if (MODE == 0) {
            *(float4*)&As[bu][a_kk][a_mm] = v;
        } else {
            As[bu][a_kk + 0][a_mm] = v.x; As[bu][a_kk + 1][a_mm] = v.y;
            As[bu][a_kk + 2][a_mm] = v.z; As[bu][a_kk + 3][a_mm] = v.w;
        }
    };
    auto stB = [&](int bu, float4 v) {
        Bs[bu][bk4 + 0][bn] = v.x; Bs[bu][bk4 + 1][bn] = v.y;
        Bs[bu][bk4 + 2][bn] = v.z; Bs[bu][bk4 + 3][bn] = v.w;
    };

    stA(0, ldA(0));
    stB(0, ldB(0));
    __syncthreads();

    int buf = 0;
    for (int kt = 0; kt < KT; ++kt) {
        float4 na, nb4;
        const bool more = (kt + 1 < KT);
        if (more) { na = ldA(kt + 1); nb4 = ldB(kt + 1); }

#pragma unroll
        for (int kk = 0; kk < 8; ++kk) {
            float4 a0 = *(const float4*)&As[buf][kk][ty * 4];
            float4 a1 = *(const float4*)&As[buf][kk][64 + ty * 4];
            ulonglong2 bv0 = *(const ulonglong2*)&Bs[buf][kk][tx * 4];
            ulonglong2 bv1 = *(const ulonglong2*)&Bs[buf][kk][64 + tx * 4];
            float av[8] = {a0.x, a0.y, a0.z, a0.w, a1.x, a1.y, a1.z, a1.w};
#pragma unroll
            for (int i = 0; i < 8; ++i) {
                unsigned long long ap = pack2(av[i]);
                ffma2(acc[i][0], ap, bv0.x);
                ffma2(acc[i][1], ap, bv0.y);
                ffma2(acc[i][2], ap, bv1.x);
                ffma2(acc[i][3], ap, bv1.y);
            }
        }

        if (more) {
            stA(buf ^ 1, na);
            stB(buf ^ 1, nb4);
            __syncthreads();
            buf ^= 1;
        }
    }

    // ---- unpack accumulators: cfr[i][0..3] = n0+tx*4+{0..3}; [4..7] = n0+64+tx*4+{0..3} ----
    float cfr[8][8];
#pragma unroll
    for (int i = 0; i < 8; ++i)
#pragma unroll
        for (int j = 0; j < 4; ++j) {
            cfr[i][2 * j]     = __uint_as_float((unsigned)acc[i][j]);
            cfr[i][2 * j + 1] = __uint_as_float((unsigned)(acc[i][j] >> 32));
        }

    int mrow[8];
#pragma unroll
    for (int i = 0; i < 8; ++i) mrow[i] = m0 + ((i < 4) ? ty * 4 + i : 64 + ty * 4 + i - 4);
    const int ncol0 = n0 + tx * 4;
    const int ncol1 = n0 + 64 + tx * 4;

    if constexpr (MODE == 0 || MODE == 2) {
        // YAT epilogue: scale * (dot+b)^2 / (||w||^2 + ||x||^2 - 2*dot + eps)
        const float* wn = (MODE == 0) ? g_twn : g_cwn;
        const float* xn = (MODE == 0) ? g_xn1 : g_xn2;
        const float sc = powf(sqrtf((float)N / logf((float)N + 1.0f)), alpha[0]);
        float xv[8];
#pragma unroll
        for (int i = 0; i < 8; ++i) xv[i] = xn[mrow[i]];
#pragma unroll
        for (int jg = 0; jg < 2; ++jg) {
            const int nb0 = jg ? ncol1 : ncol0;
            float wv[4], bv[4];
#pragma unroll
            for (int jj = 0; jj < 4; ++jj) { wv[jj] = wn[nb0 + jj]; bv[jj] = bias[nb0 + jj]; }
#pragma unroll
            for (int i = 0; i < 8; ++i) {
                float4 r;
                float* rp = (float*)&r;
#pragma unroll
                for (int jj = 0; jj < 4; ++jj) {
                    float d  = cfr[i][jg * 4 + jj];
                    float dt = d + bv[jj];
                    float ds = wv[jj] + xv[i] - 2.0f * d + EPSV;
                    rp[jj] = sc * dt * dt / ds;
                }
                *(float4*)&out[(long)mrow[i] * N + nb0] = r;
            }
        }
    }

    if constexpr (MODE == 1) {
        // residual + transpose: X2[(b,p=n,c)] = x + acc + b2[n]; m=(b,c)
        const float* res = resArg;   // x
        const int bidx = m0 / 768;
#pragma unroll
        for (int ig = 0; ig < 2; ++ig) {
            const int mstart = m0 + (ig ? 64 : 0) + ty * 4;
            const int cc = mstart % 768;
#pragma unroll
            for (int j = 0; j < 8; ++j) {
                const int ngl = (j < 4) ? (n0 + tx * 4 + j) : (n0 + 64 + tx * 4 + j - 4);
                if (!NRAG || ngl < N) {
                    const long o = ((long)(bidx * 196 + ngl)) * 768 + cc;
                    float4 xv4 = *(const float4*)&res[o];
                    const float bj = bias[ngl];
                    float4 r;
                    r.x = xv4.x + cfr[ig * 4 + 0][j] + bj;
                    r.y = xv4.y + cfr[ig * 4 + 1][j] + bj;
                    r.z = xv4.z + cfr[ig * 4 + 2][j] + bj;
                    r.w = xv4.w + cfr[ig * 4 + 3][j] + bj;
                    *(float4*)&out[o] = r;
                }
            }
        }
    }

    if constexpr (MODE == 3) {
        // residual, row-major: out[m,n] = X2[m,n] + acc + b4[n]
        const float* res = g_X2;
#pragma unroll
        for (int i = 0; i < 8; ++i) {
#pragma unroll
            for (int jg = 0; jg < 2; ++jg) {
                const int nb0 = jg ? ncol1 : ncol0;
                const long o = (long)mrow[i] * N + nb0;
                float4 rv = *(const float4*)&res[o];
                float4 r;
                r.x = rv.x + cfr[i][jg * 4 + 0] + bias[nb0 + 0];
                r.y = rv.y + cfr[i][jg * 4 + 1] + bias[nb0 + 1];
                r.z = rv.z + cfr[i][jg * 4 + 2] + bias[nb0 + 2];
                r.w = rv.w + cfr[i][jg * 4 + 3] + bias[nb0 + 3];
                *(float4*)&out[o] = r;
            }
        }
    }
}

// ---------------------------------------------------------------------------
extern "C" void kernel_launch(void* const* d_in, const int* in_sizes, int n_in,
                              void* d_out, int out_size) {
    (void)in_sizes; (void)n_in; (void)out_size;
    const float* x  = (const float*)d_in[0];
    const float* tw = (const float*)d_in[1];
    const float* tb = (const float*)d_in[2];
    const float* ta = (const float*)d_in[3];
    const float* w2 = (const float*)d_in[4];
    const float* b2 = (const float*)d_in[5];
    const float* cw = (const float*)d_in[6];
    const float* cb = (const float*)d_in[7];
    const float* ca = (const float*)d_in[8];
    const float* w4 = (const float*)d_in[9];
    const float* b4 = (const float*)d_in[10];
    float* outp = (float*)d_out;

    // weight norms + x norms (token path)
    rownorm_kernel<<<96, 128>>>(tw, 384, 196, 0);     // g_twn
    rownorm_kernel<<<768, 128>>>(cw, 3072, 768, 1);   // g_cwn
    xnorm1_kernel<<<192, 256>>>(x);                   // g_xn1

    // token mixing
    gemm_kernel<0><<<dim3(3, 384), 256>>>(x, tw, tb, ta, nullptr, nullptr);        // -> g_H1
    gemm_kernel<1><<<dim3(2, 384), 256>>>(nullptr, w2, b2, nullptr, x, nullptr);   // -> g_X2

    // channel mixing
    rownorm_kernel<<<3136, 128>>>(nullptr, 12544, 768, 2);                          // g_xn2
    gemm_kernel<2><<<dim3(24, 98), 256>>>(nullptr, cw, cb, ca, nullptr, nullptr);   // -> g_H3
    gemm_kernel<3><<<dim3(6, 98), 256>>>(nullptr, w4, b4, nullptr, nullptr, outp);  // -> out
}

// round 7
// speedup vs baseline: 1.9420x; 1.9420x over previous
#include <cuda_runtime.h>
#include <cstdint>

#define EPSV 0.1f
#define SWZ(x) ((x) ^ (((x) >> 3) & 0x70))

// tcgen05 only compiles on arch-specific / family-specific targets.
#if defined(__CUDA_ARCH_FEAT_SM103_ALL) || defined(__CUDA_ARCH_FAMILY_SPECIFIC__) || defined(__CUDA_ARCH_FEAT_SM100_ALL)
#define TC_ENABLED 1
#else
#define TC_ENABLED 0
#endif

// ---------------- scratch globals (no allocations allowed) ----------------
__device__ __align__(1024) float g_H1[49152L * 384];    // token YAT out
__device__ __align__(1024) float g_X2[12544L * 768];    // after token mixing (b,p,c)
__device__ __align__(1024) float g_H3[12544L * 3072];   // channel YAT out
__device__ float g_xn1[49152];
__device__ float g_xn2[12544];
__device__ float g_twn[384];
__device__ float g_cwn[3072];

// ---------------- fp32x2 helpers (packed FFMA2) ----------------
__device__ __forceinline__ void ffma2(unsigned long long &d,
                                      unsigned long long a,
                                      unsigned long long b) {
    asm("fma.rn.f32x2 %0, %1, %2, %0;" : "+l"(d) : "l"(a), "l"(b));
}
__device__ __forceinline__ unsigned long long pack2(float x) {
    unsigned long long r;
    unsigned u = __float_as_uint(x);
    asm("mov.b64 %0, {%1, %1};" : "=l"(r) : "r"(u));
    return r;
}

// ---------------- mbarrier / tcgen05 helpers (inlined only when used) ------
__device__ __forceinline__ uint32_t smem_u32(const void* p) {
    uint32_t a;
    asm("{ .reg .u64 t; cvta.to.shared.u64 t, %1; cvt.u32.u64 %0, t; }" : "=r"(a) : "l"(p));
    return a;
}
#if TC_ENABLED
__device__ __forceinline__ void mbar_init(uint32_t a, uint32_t c) {
    asm volatile("mbarrier.init.shared.b64 [%0], %1;" :: "r"(a), "r"(c) : "memory");
}
__device__ __forceinline__ void mbar_arrive(uint32_t a) {
    asm volatile("mbarrier.arrive.shared.b64 _, [%0];" :: "r"(a) : "memory");
}
__device__ __forceinline__ void mbar_wait(uint32_t a, uint32_t ph) {
    asm volatile(
        "{\n\t.reg .pred P;\n"
        "W_%=:\n\t"
        "mbarrier.try_wait.parity.acquire.cta.shared::cta.b64 P, [%0], %1, 0x989680;\n\t"
        "@P bra.uni D_%=;\n\t"
        "bra.uni W_%=;\n"
        "D_%=:\n\t}"
        :: "r"(a), "r"(ph) : "memory");
}
__device__ __forceinline__ void tmem_alloc(uint32_t dst, uint32_t n) {
    asm volatile("tcgen05.alloc.cta_group::1.sync.aligned.shared::cta.b32 [%0], %1;"
                 :: "r"(dst), "r"(n) : "memory");
}
__device__ __forceinline__ void tmem_dealloc(uint32_t t, uint32_t n) {
    asm volatile("tcgen05.relinquish_alloc_permit.cta_group::1.sync.aligned;");
    asm volatile("tcgen05.dealloc.cta_group::1.sync.aligned.b32 %0, %1;" :: "r"(t), "r"(n));
}
__device__ __forceinline__ void mma_tf32(uint32_t d, uint64_t ad, uint64_t bd,
                                         uint32_t idesc, uint32_t en) {
    asm volatile(
        "{\n\t.reg .pred p;\n\tsetp.ne.u32 p, %4, 0;\n\t"
        "tcgen05.mma.cta_group::1.kind::tf32 [%0], %1, %2, %3, {%5,%5,%5,%5}, p;\n\t}"
        :: "r"(d), "l"(ad), "l"(bd), "r"(idesc), "r"(en), "r"(0u) : "memory");
}
__device__ __forceinline__ void mma_commit(uint32_t mbar) {
    asm volatile("tcgen05.commit.cta_group::1.mbarrier::arrive::one.shared::cluster.b64 [%0];"
                 :: "r"(mbar) : "memory");
}
#define TC_FENCE_AFTER()     asm volatile("tcgen05.fence::after_thread_sync;" ::: "memory")
#define TC_FENCE_BEFORE()    asm volatile("tcgen05.fence::before_thread_sync;" ::: "memory")
#define TMEM_WAIT_LD()       asm volatile("tcgen05.wait::ld.sync.aligned;" ::: "memory")
#define FENCE_ASYNC_SHARED() asm volatile("fence.proxy.async.shared::cta;" ::: "memory")

#define LDTM_X32(r, a) \
    asm volatile( \
        "tcgen05.ld.sync.aligned.32x32b.x32.b32 " \
        "{%0, %1, %2, %3, %4, %5, %6, %7, " \
        " %8, %9, %10, %11, %12, %13, %14, %15, " \
        " %16, %17, %18, %19, %20, %21, %22, %23, " \
        " %24, %25, %26, %27, %28, %29, %30, %31}, [%32];" \
        : "=r"((r)[0]),  "=r"((r)[1]),  "=r"((r)[2]),  "=r"((r)[3]), \
          "=r"((r)[4]),  "=r"((r)[5]),  "=r"((r)[6]),  "=r"((r)[7]), \
          "=r"((r)[8]),  "=r"((r)[9]),  "=r"((r)[10]), "=r"((r)[11]), \
          "=r"((r)[12]), "=r"((r)[13]), "=r"((r)[14]), "=r"((r)[15]), \
          "=r"((r)[16]), "=r"((r)[17]), "=r"((r)[18]), "=r"((r)[19]), \
          "=r"((r)[20]), "=r"((r)[21]), "=r"((r)[22]), "=r"((r)[23]), \
          "=r"((r)[24]), "=r"((r)[25]), "=r"((r)[26]), "=r"((r)[27]), \
          "=r"((r)[28]), "=r"((r)[29]), "=r"((r)[30]), "=r"((r)[31]) \
        : "r"(a))
#endif  // TC_ENABLED

__device__ __forceinline__ void tf32_split(float v, uint32_t& h, uint32_t& l) {
    asm("cvt.rna.tf32.f32 %0, %1;" : "=r"(h) : "f"(v));
    float r = v - __uint_as_float(h);
    asm("cvt.rna.tf32.f32 %0, %1;" : "=r"(l) : "f"(r));
}

// SW128 K-major SMEM descriptor base: LBO=1, SBO=64, layout=2, ver=1
static constexpr unsigned long long DESC_BASE =
    (1ull << 62) | (1ull << 46) | (64ull << 32) | (1ull << 16);  // layout_type=2 -> bit pattern 2<<61
// (2<<61) == (1<<62); keep explicit:
static_assert(DESC_BASE == ((2ull << 61) | (1ull << 46) | (64ull << 32) | (1ull << 16)), "desc");
// idesc: dtype=F32(1)<<4, atype=TF32(2)<<7, btype=TF32(2)<<10, N/8<<17, M/16<<24
static constexpr uint32_t IDESC_TF32 =
    (1u << 4) | (2u << 7) | (2u << 10) | ((256 / 8) << 17) | ((128 / 16) << 24);

// ---------------- small prep kernels ----------------
__global__ void rownorm_kernel(const float* __restrict__ srcArg, int rows, int K, int sel) {
    const float* src = (sel == 2) ? g_X2 : srcArg;
    float* dst = (sel == 0) ? g_twn : (sel == 1) ? g_cwn : g_xn2;
    int row = blockIdx.x * 4 + (threadIdx.x >> 5);
    if (row >= rows) return;
    int lane = threadIdx.x & 31;
    const float* p = src + (long)row * K;
    float s = 0.f;
    for (int k = lane; k < K; k += 32) { float v = p[k]; s = fmaf(v, v, s); }
#pragma unroll
    for (int o = 16; o; o >>= 1) s += __shfl_xor_sync(0xffffffffu, s, o);
    if (lane == 0) dst[row] = s;
}

__global__ void xnorm1_kernel(const float* __restrict__ x) {
    int g = blockIdx.x * blockDim.x + threadIdx.x;   // < 49152
    int b = g / 768, c = g - b * 768;
    const float* p = x + (long)b * 196 * 768 + c;
    float s = 0.f;
#pragma unroll 4
    for (int i = 0; i < 196; ++i) { float v = p[(long)i * 768]; s = fmaf(v, v, s); }
    g_xn1[g] = s;
}

// ---------------------------------------------------------------------------
// SIMT FFMA2 GEMM, token path (MODE 0: token YAT, MODE 1: token mix+residual).
// ---------------------------------------------------------------------------
template<int MODE>
__global__ __launch_bounds__(256, 2) void gemm_kernel(
    const float* __restrict__ Aarg,
    const float* __restrict__ W,
    const float* __restrict__ bias,
    const float* __restrict__ alpha,
    const float* __restrict__ resArg)
{
    constexpr int N  = (MODE == 0) ? 384 : 196;
    constexpr int K  = (MODE == 0) ? 196 : 384;
    constexpr int KT = (K + 7) / 8;
    constexpr bool KRAG = (K % 8) != 0;
    constexpr bool NRAG = (N % 128) != 0;

    const float* A = (MODE == 0) ? Aarg : g_H1;
    float* out = (MODE == 0) ? g_H1 : g_X2;

    __shared__ float As[2][8][132];
    __shared__ float Bs[2][8][132];

    const int tid = threadIdx.x;
    const int m0 = blockIdx.y * 128;
    const int n0 = blockIdx.x * 128;

    const int bn  = tid >> 1;
    const int bk4 = (tid & 1) * 4;
    const int gnb = n0 + bn;
    const bool bnOK = !NRAG || (gnb < N);
    const float* Bptr = W + (long)gnb * K + bk4;

    int a_kk, a_mm;
    const float* Aptr;
    if (MODE == 0) {
        a_kk = tid >> 5;
        a_mm = (tid & 31) * 4;
        const int b = m0 / 768;
        const int c = (m0 % 768) + a_mm;
        Aptr = A + ((long)(b * 196 + a_kk)) * 768 + c;
    } else {
        a_mm = tid >> 1;
        a_kk = (tid & 1) * 4;
        Aptr = A + (long)(m0 + a_mm) * K + a_kk;
    }

    const int tx = tid & 15;
    const int ty = tid >> 4;

    unsigned long long acc[8][4];
#pragma unroll
    for (int i = 0; i < 8; ++i)
#pragma unroll
        for (int j = 0; j < 4; ++j) acc[i][j] = 0ull;

    auto ldA = [&](int kt) -> float4 {
        if (MODE == 0) {
            if (!KRAG || (kt * 8 + a_kk) < K)
                return *(const float4*)(Aptr + (long)kt * 8 * 768);
            return make_float4(0.f, 0.f, 0.f, 0.f);
        } else {
            return *(const float4*)(Aptr + kt * 8);
        }
    };
    auto ldB = [&](int kt) -> float4 {
        bool ok = bnOK && (!KRAG || (kt * 8 + bk4) < K);
        if (ok) return *(const float4*)(Bptr + kt * 8);
        return make_float4(0.f, 0.f, 0.f, 0.f);
    };
    auto stA = [&](int bu, float4 v) {
        if (MODE == 0) {
            *(float4*)&As[bu][a_kk][a_mm] = v;
        } else {
            As[bu][a_kk + 0][a_mm] = v.x; As[bu][a_kk + 1][a_mm] = v.y;
            As[bu][a_kk + 2][a_mm] = v.z; As[bu][a_kk + 3][a_mm] = v.w;
        }
    };
    auto stB = [&](int bu, float4 v) {
        Bs[bu][bk4 + 0][bn] = v.x; Bs[bu][bk4 + 1][bn] = v.y;
        Bs[bu][bk4 + 2][bn] = v.z; Bs[bu][bk4 + 3][bn] = v.w;
    };

    stA(0, ldA(0));
    stB(0, ldB(0));
    __syncthreads();

    int buf = 0;
    for (int kt = 0; kt < KT; ++kt) {
        float4 na, nb4;
        const bool more = (kt + 1 < KT);
        if (more) { na = ldA(kt + 1); nb4 = ldB(kt + 1); }

#pragma unroll
        for (int kk = 0; kk < 8; ++kk) {
            float4 a0 = *(const float4*)&As[buf][kk][ty * 4];
            float4 a1 = *(const float4*)&As[buf][kk][64 + ty * 4];
            ulonglong2 bv0 = *(const ulonglong2*)&Bs[buf][kk][tx * 4];
            ulonglong2 bv1 = *(const ulonglong2*)&Bs[buf][kk][64 + tx * 4];
            float av[8] = {a0.x, a0.y, a0.z, a0.w, a1.x, a1.y, a1.z, a1.w};
#pragma unroll
            for (int i = 0; i < 8; ++i) {
                unsigned long long ap = pack2(av[i]);
                ffma2(acc[i][0], ap, bv0.x);
                ffma2(acc[i][1], ap, bv0.y);
                ffma2(acc[i][2], ap, bv1.x);
                ffma2(acc[i][3], ap, bv1.y);
            }
        }

        if (more) {
            stA(buf ^ 1, na);
            stB(buf ^ 1, nb4);
            __syncthreads();
            buf ^= 1;
        }
    }

    float cfr[8][8];
#pragma unroll
    for (int i = 0; i < 8; ++i)
#pragma unroll
        for (int j = 0; j < 4; ++j) {
            cfr[i][2 * j]     = __uint_as_float((unsigned)acc[i][j]);
            cfr[i][2 * j + 1] = __uint_as_float((unsigned)(acc[i][j] >> 32));
        }

    int mrow[8];
#pragma unroll
    for (int i = 0; i < 8; ++i) mrow[i] = m0 + ((i < 4) ? ty * 4 + i : 64 + ty * 4 + i - 4);
    const int ncol0 = n0 + tx * 4;
    const int ncol1 = n0 + 64 + tx * 4;

    if constexpr (MODE == 0) {
        const float sc = powf(sqrtf((float)N / logf((float)N + 1.0f)), alpha[0]);
        float xv[8];
#pragma unroll
        for (int i = 0; i < 8; ++i) xv[i] = g_xn1[mrow[i]];
#pragma unroll
        for (int jg = 0; jg < 2; ++jg) {
            const int nb0 = jg ? ncol1 : ncol0;
            float wv[4], bv[4];
#pragma unroll
            for (int jj = 0; jj < 4; ++jj) { wv[jj] = g_twn[nb0 + jj]; bv[jj] = bias[nb0 + jj]; }
#pragma unroll
            for (int i = 0; i < 8; ++i) {
                float4 r;
                float* rp = (float*)&r;
#pragma unroll
                for (int jj = 0; jj < 4; ++jj) {
                    float d  = cfr[i][jg * 4 + jj];
                    float dt = d + bv[jj];
                    float ds = wv[jj] + xv[i] - 2.0f * d + EPSV;
                    rp[jj] = sc * dt * dt / ds;
                }
                *(float4*)&out[(long)mrow[i] * N + nb0] = r;
            }
        }
    }

    if constexpr (MODE == 1) {
        const float* res = resArg;   // x
        const int bidx = m0 / 768;
#pragma unroll
        for (int ig = 0; ig < 2; ++ig) {
            const int mstart = m0 + (ig ? 64 : 0) + ty * 4;
            const int cc = mstart % 768;
#pragma unroll
            for (int j = 0; j < 8; ++j) {
                const int ngl = (j < 4) ? (n0 + tx * 4 + j) : (n0 + 64 + tx * 4 + j - 4);
                if (ngl < N) {
                    const long o = ((long)(bidx * 196 + ngl)) * 768 + cc;
                    float4 xv4 = *(const float4*)&res[o];
                    const float bj = bias[ngl];
                    float4 r;
                    r.x = xv4.x + cfr[ig * 4 + 0][j] + bj;
                    r.y = xv4.y + cfr[ig * 4 + 1][j] + bj;
                    r.z = xv4.z + cfr[ig * 4 + 2][j] + bj;
                    r.w = xv4.w + cfr[ig * 4 + 3][j] + bj;
                    *(float4*)&out[o] = r;
                }
            }
        }
    }
}

// ---------------------------------------------------------------------------
// Channel-path GEMM.  C[m,n] = sum_k A[m,k] * W[n,k];  tile 128(M) x 256(N).
// MODE 2: A = g_X2 (K=768),  N=3072, epilogue = channel YAT -> g_H3
// MODE 3: A = g_H3 (K=3072), N=768,  epilogue = residual(g_X2)+bias -> out
// tcgen05 3xTF32 on sm_103a/f builds; SIMT FFMA2 fallback on plain sm_103.
// ---------------------------------------------------------------------------
#define TC_SMEM_BYTES (5120 + 2 * 98304)

template<int MODE>
__global__ __launch_bounds__(256, 1) void gemm_tc(
    const float* __restrict__ Wt,
    const float* __restrict__ bias,
    const float* __restrict__ alpha,
    float* __restrict__ outArg)
{
    constexpr int N = (MODE == 2) ? 3072 : 768;
    constexpr int K = (MODE == 2) ? 768 : 3072;
    const float* A = (MODE == 2) ? g_X2 : g_H3;
    float* out = (MODE == 2) ? g_H3 : outArg;

    extern __shared__ char smem[];

#if TC_ENABLED
    constexpr int NCH = K / 32;
    const uint32_t sb = smem_u32(smem);
    const uint32_t FULL0 = sb + 16, EMPTY0 = sb + 32, DONE = sb + 48;
    const uint32_t stage0 = (sb + 4096 + 1023) & ~1023u;  // 1024-aligned stage base
    char* stage_ptr0 = smem + (stage0 - sb);
    float* lutW = (float*)(smem + 1024);
    float* lutB = (float*)(smem + 2048);

    const int tid = threadIdx.x;
    const int wid = tid >> 5, lane = tid & 31;
    const int m0 = blockIdx.y * 128;
    const int n0 = blockIdx.x * 256;

    if (tid == 0) {
        mbar_init(FULL0, 256);  mbar_init(FULL0 + 8, 256);
        mbar_init(EMPTY0, 1);   mbar_init(EMPTY0 + 8, 1);
        mbar_init(DONE, 1);
    }
    if (wid == 0) tmem_alloc(sb, 256);
    if constexpr (MODE == 2) lutW[tid] = g_cwn[n0 + tid];
    lutB[tid] = bias[n0 + tid];
    __syncthreads();
    uint32_t tmem;
    asm volatile("ld.shared.b32 %0, [%1];" : "=r"(tmem) : "r"(sb));

    // producer mapping: 8 threads cover one 128B row
    const int r8 = tid >> 3;          // 0..31
    const int c8 = (tid & 7) * 4;     // fp32 col 0..28

    for (int t = 0; t < NCH; ++t) {
        const int s = t & 1;
        if (t >= 2) mbar_wait(EMPTY0 + s * 8, ((t >> 1) - 1) & 1);
        char* st = stage_ptr0 + s * 98304;
        const int kc = t * 32;
#pragma unroll
        for (int q = 0; q < 4; ++q) {   // A: 128 rows x 32 fp32
            const int row = q * 32 + r8;
            float4 v = *(const float4*)(A + (long)(m0 + row) * K + kc + c8);
            uint32_t h0,h1,h2,h3,l0,l1,l2,l3;
            tf32_split(v.x, h0, l0); tf32_split(v.y, h1, l1);
            tf32_split(v.z, h2, l2); tf32_split(v.w, h3, l3);
            const uint32_t o = SWZ((uint32_t)(row * 128 + (tid & 7) * 16));
            *(uint4*)(st + o)         = make_uint4(h0, h1, h2, h3);
            *(uint4*)(st + 16384 + o) = make_uint4(l0, l1, l2, l3);
        }
#pragma unroll
        for (int q = 0; q < 8; ++q) {   // B: 256 rows x 32 fp32
            const int row = q * 32 + r8;
            float4 v = *(const float4*)(Wt + (long)(n0 + row) * K + kc + c8);
            uint32_t h0,h1,h2,h3,l0,l1,l2,l3;
            tf32_split(v.x, h0, l0); tf32_split(v.y, h1, l1);
            tf32_split(v.z, h2, l2); tf32_split(v.w, h3, l3);
            const uint32_t o = SWZ((uint32_t)(row * 128 + (tid & 7) * 16));
            *(uint4*)(st + 32768 + o) = make_uint4(h0, h1, h2, h3);
            *(uint4*)(st + 65536 + o) = make_uint4(l0, l1, l2, l3);
        }
        FENCE_ASYNC_SHARED();
        mbar_arrive(FULL0 + s * 8);

        if (tid == 0) {
            mbar_wait(FULL0 + s * 8, (t >> 1) & 1);
            const uint32_t sa = stage0 + s * 98304;
            const uint64_t dah = DESC_BASE | ((uint64_t)(sa >> 4) & 0x3FFF);
            const uint64_t dal = DESC_BASE | ((uint64_t)((sa + 16384) >> 4) & 0x3FFF);
            const uint64_t dbh = DESC_BASE | ((uint64_t)((sa + 32768) >> 4) & 0x3FFF);
            const uint64_t dbl = DESC_BASE | ((uint64_t)((sa + 65536) >> 4) & 0x3FFF);
#pragma unroll
            for (int ks = 0; ks < 4; ++ks) {
                const uint32_t en = (t > 0 || ks > 0) ? 1u : 0u;
                mma_tf32(tmem, dah + ks * 2, dbh + ks * 2, IDESC_TF32, en);
                mma_tf32(tmem, dah + ks * 2, dbl + ks * 2, IDESC_TF32, 1u);
                mma_tf32(tmem, dal + ks * 2, dbh + ks * 2, IDESC_TF32, 1u);
            }
            mma_commit(EMPTY0 + s * 8);
        }
    }
    if (tid == 0) mma_commit(DONE);
    mbar_wait(DONE, 0);
    TC_FENCE_AFTER();

    // epilogue: warps 0-3 -> cols [0,128), warps 4-7 -> cols [128,256)
    const long m = m0 + (wid & 3) * 32 + lane;
    const int cb0 = (wid >> 2) * 128;
    float sc = 0.f, xv = 0.f;
    if constexpr (MODE == 2) {
        sc = powf(sqrtf((float)N / logf((float)N + 1.0f)), alpha[0]);
        xv = g_xn2[m];
    }
#pragma unroll
    for (int cs = 0; cs < 4; ++cs) {
        uint32_t r[32];
        LDTM_X32(r, tmem + cb0 + cs * 32);
        TMEM_WAIT_LD();
        const int nb = cb0 + cs * 32;
        float* orow = out + m * N + n0 + nb;
        if constexpr (MODE == 2) {
#pragma unroll
            for (int q = 0; q < 8; ++q) {
                float4 o;
                float* op = (float*)&o;
#pragma unroll
                for (int jj = 0; jj < 4; ++jj) {
                    const int j = q * 4 + jj;
                    const float d  = __uint_as_float(r[j]);
                    const float dt = d + lutB[nb + j];
                    const float ds = lutW[nb + j] + xv - 2.0f * d + EPSV;
                    op[jj] = sc * dt * dt / ds;
                }
                *(float4*)(orow + q * 4) = o;
            }
        } else {
            const float* rrow = g_X2 + m * 768 + n0 + nb;
#pragma unroll
            for (int q = 0; q < 8; ++q) {
                const float4 rv = *(const float4*)(rrow + q * 4);
                float4 o;
                o.x = rv.x + __uint_as_float(r[q * 4 + 0]) + lutB[nb + q * 4 + 0];
                o.y = rv.y + __uint_as_float(r[q * 4 + 1]) + lutB[nb + q * 4 + 1];
                o.z = rv.z + __uint_as_float(r[q * 4 + 2]) + lutB[nb + q * 4 + 2];
                o.w = rv.w + __uint_as_float(r[q * 4 + 3]) + lutB[nb + q * 4 + 3];
                *(float4*)(orow + q * 4) = o;
            }
        }
    }
    TC_FENCE_BEFORE();
    __syncthreads();
    if (wid == 0) tmem_dealloc(tmem, 256);

#else   // ---------------- SIMT FFMA2 fallback (plain sm_103 build) --------
    float (*As)[8][132] = reinterpret_cast<float(*)[8][132]>(smem);
    float (*Bs)[8][132] = reinterpret_cast<float(*)[8][132]>(smem + 2 * 8 * 132 * 4);

    constexpr int KT = K / 8;
    const int tid = threadIdx.x;
    const int m0 = blockIdx.y * 128;
    const int bn  = tid >> 1;
    const int bk4 = (tid & 1) * 4;
    const int a_mm = tid >> 1;
    const int a_kk = (tid & 1) * 4;
    const int tx = tid & 15;
    const int ty = tid >> 4;

    for (int half = 0; half < 2; ++half) {
        const int n0 = blockIdx.x * 256 + half * 128;
        const float* Aptr = A + (long)(m0 + a_mm) * K + a_kk;
        const float* Bptr = Wt + (long)(n0 + bn) * K + bk4;

        unsigned long long acc[8][4];
#pragma unroll
        for (int i = 0; i < 8; ++i)
#pragma unroll
            for (int j = 0; j < 4; ++j) acc[i][j] = 0ull;

        if (half) __syncthreads();
        {
            float4 va = *(const float4*)(Aptr);
            float4 vb = *(const float4*)(Bptr);
            As[0][a_kk + 0][a_mm] = va.x; As[0][a_kk + 1][a_mm] = va.y;
            As[0][a_kk + 2][a_mm] = va.z; As[0][a_kk + 3][a_mm] = va.w;
            Bs[0][bk4 + 0][bn] = vb.x; Bs[0][bk4 + 1][bn] = vb.y;
            Bs[0][bk4 + 2][bn] = vb.z; Bs[0][bk4 + 3][bn] = vb.w;
        }
        __syncthreads();

        int buf = 0;
        for (int kt = 0; kt < KT; ++kt) {
            float4 na, nb4;
            const bool more = (kt + 1 < KT);
            if (more) {
                na  = *(const float4*)(Aptr + (kt + 1) * 8);
                nb4 = *(const float4*)(Bptr + (kt + 1) * 8);
            }
#pragma unroll
            for (int kk = 0; kk < 8; ++kk) {
                float4 a0 = *(const float4*)&As[buf][kk][ty * 4];
                float4 a1 = *(const float4*)&As[buf][kk][64 + ty * 4];
                ulonglong2 bv0 = *(const ulonglong2*)&Bs[buf][kk][tx * 4];
                ulonglong2 bv1 = *(const ulonglong2*)&Bs[buf][kk][64 + tx * 4];
                float av[8] = {a0.x, a0.y, a0.z, a0.w, a1.x, a1.y, a1.z, a1.w};
#pragma unroll
                for (int i = 0; i < 8; ++i) {
                    unsigned long long ap = pack2(av[i]);
                    ffma2(acc[i][0], ap, bv0.x);
                    ffma2(acc[i][1], ap, bv0.y);
                    ffma2(acc[i][2], ap, bv1.x);
                    ffma2(acc[i][3], ap, bv1.y);
                }
            }
            if (more) {
                As[buf ^ 1][a_kk + 0][a_mm] = na.x; As[buf ^ 1][a_kk + 1][a_mm] = na.y;
                As[buf ^ 1][a_kk + 2][a_mm] = na.z; As[buf ^ 1][a_kk + 3][a_mm] = na.w;
                Bs[buf ^ 1][bk4 + 0][bn] = nb4.x; Bs[buf ^ 1][bk4 + 1][bn] = nb4.y;
                Bs[buf ^ 1][bk4 + 2][bn] = nb4.z; Bs[buf ^ 1][bk4 + 3][bn] = nb4.w;
                __syncthreads();
                buf ^= 1;
            }
        }

        float cfr[8][8];
#pragma unroll
        for (int i = 0; i < 8; ++i)
#pragma unroll
            for (int j = 0; j < 4; ++j) {
                cfr[i][2 * j]     = __uint_as_float((unsigned)acc[i][j]);
                cfr[i][2 * j + 1] = __uint_as_float((unsigned)(acc[i][j] >> 32));
            }

        int mrow[8];
#pragma unroll
        for (int i = 0; i < 8; ++i) mrow[i] = m0 + ((i < 4) ? ty * 4 + i : 64 + ty * 4 + i - 4);
        const int ncol0 = n0 + tx * 4;
        const int ncol1 = n0 + 64 + tx * 4;

        if constexpr (MODE == 2) {
            const float sc = powf(sqrtf((float)N / logf((float)N + 1.0f)), alpha[0]);
            float xv[8];
#pragma unroll
            for (int i = 0; i < 8; ++i) xv[i] = g_xn2[mrow[i]];
#pragma unroll
            for (int jg = 0; jg < 2; ++jg) {
                const int nb0 = jg ? ncol1 : ncol0;
                float wv[4], bv[4];
#pragma unroll
                for (int jj = 0; jj < 4; ++jj) { wv[jj] = g_cwn[nb0 + jj]; bv[jj] = bias[nb0 + jj]; }
#pragma unroll
                for (int i = 0; i < 8; ++i) {
                    float4 r;
                    float* rp = (float*)&r;
#pragma unroll
                    for (int jj = 0; jj < 4; ++jj) {
                        float d  = cfr[i][jg * 4 + jj];
                        float dt = d + bv[jj];
                        float ds = wv[jj] + xv[i] - 2.0f * d + EPSV;
                        rp[jj] = sc * dt * dt / ds;
                    }
                    *(float4*)&out[(long)mrow[i] * N + nb0] = r;
                }
            }
        } else {
#pragma unroll
            for (int i = 0; i < 8; ++i) {
#pragma unroll
                for (int jg = 0; jg < 2; ++jg) {
                    const int nb0 = jg ? ncol1 : ncol0;
                    const long o = (long)mrow[i] * N + nb0;
                    float4 rv = *(const float4*)&g_X2[o];
                    float4 r;
                    r.x = rv.x + cfr[i][jg * 4 + 0] + bias[nb0 + 0];
                    r.y = rv.y + cfr[i][jg * 4 + 1] + bias[nb0 + 1];
                    r.z = rv.z + cfr[i][jg * 4 + 2] + bias[nb0 + 2];
                    r.w = rv.w + cfr[i][jg * 4 + 3] + bias[nb0 + 3];
                    *(float4*)&out[o] = r;
                }
            }
        }
    }
#endif  // TC_ENABLED
}

// ---------------------------------------------------------------------------
extern "C" void kernel_launch(void* const* d_in, const int* in_sizes, int n_in,
                              void* d_out, int out_size) {
    (void)in_sizes; (void)n_in; (void)out_size;
    const float* x  = (const float*)d_in[0];
    const float* tw = (const float*)d_in[1];
    const float* tb = (const float*)d_in[2];
    const float* ta = (const float*)d_in[3];
    const float* w2 = (const float*)d_in[4];
    const float* b2 = (const float*)d_in[5];
    const float* cw = (const float*)d_in[6];
    const float* cb = (const float*)d_in[7];
    const float* ca = (const float*)d_in[8];
    const float* w4 = (const float*)d_in[9];
    const float* b4 = (const float*)d_in[10];
    float* outp = (float*)d_out;

    static int smem_set = 0;
    if (!smem_set) {
        cudaFuncSetAttribute(gemm_tc<2>, cudaFuncAttributeMaxDynamicSharedMemorySize, TC_SMEM_BYTES);
        cudaFuncSetAttribute(gemm_tc<3>, cudaFuncAttributeMaxDynamicSharedMemorySize, TC_SMEM_BYTES);
        smem_set = 1;
    }

    // norms
    rownorm_kernel<<<96, 128>>>(tw, 384, 196, 0);     // g_twn
    rownorm_kernel<<<768, 128>>>(cw, 3072, 768, 1);   // g_cwn
    xnorm1_kernel<<<192, 256>>>(x);                   // g_xn1

    // token mixing (SIMT FFMA2)
    gemm_kernel<0><<<dim3(3, 384), 256>>>(x, tw, tb, ta, nullptr);      // -> g_H1
    gemm_kernel<1><<<dim3(2, 384), 256>>>(nullptr, w2, b2, nullptr, x); // -> g_X2

    // channel mixing (tcgen05 3xTF32, or FFMA2 fallback on plain sm_103)
    rownorm_kernel<<<3136, 128>>>(nullptr, 12544, 768, 2);                  // g_xn2
    gemm_tc<2><<<dim3(12, 98), 256, TC_SMEM_BYTES>>>(cw, cb, ca, nullptr);  // -> g_H3
    gemm_tc<3><<<dim3(3, 98), 256, TC_SMEM_BYTES>>>(w4, b4, nullptr, outp); // -> out
}

// round 9
// speedup vs baseline: 3.0611x; 1.5763x over previous
#include <cuda_runtime.h>
#include <cstdint>

#define EPSV 0.1f

// tcgen05 compiles only on arch/family-specific targets (sm_103a/f), not plain sm_103.
#if defined(__CUDA_ARCH_FEAT_SM103_ALL) || defined(__CUDA_ARCH_FAMILY_SPECIFIC__) || defined(__CUDA_ARCH_FEAT_SM100_ALL)
#define TC_ENABLED 1
#else
#define TC_ENABLED 0
#endif

// ---------------- scratch globals (no allocations allowed) ----------------
__device__ __align__(1024) float g_xt [49152L * 224];   // x^T, (b*768+c, p) padded K=224
__device__ __align__(1024) float g_twp[384L * 224];     // tw padded K 196->224
__device__ __align__(1024) float g_w2p[256L * 384];     // w2 padded rows 196->256
__device__ __align__(1024) float g_H1 [49152L * 384];   // token YAT out
__device__ __align__(1024) float g_X2 [12544L * 768];   // after token mixing (b,p,c)
__device__ __align__(1024) float g_H3 [12544L * 3072];  // channel YAT out
__device__ float g_xn1[49152];
__device__ float g_xn2[12544];
__device__ float g_twn[384];
__device__ float g_cwn[3072];

// ---------------- helpers ----------------
__device__ __forceinline__ uint32_t smem_u32(const void* p) {
    uint32_t a;
    asm("{ .reg .u64 t; cvta.to.shared.u64 t, %1; cvt.u32.u64 %0, t; }" : "=r"(a) : "l"(p));
    return a;
}

// mask-based tf32 hi/lo split: h = top-10-mantissa truncation, l = masked remainder.
// All fixed-latency alu/fma ops (LOP3/FADD), rt=2 per SMSP.
__device__ __forceinline__ uint2 msplit(float v) {
    uint32_t u = __float_as_uint(v);
    uint32_t h = u & 0xFFFFE000u;
    float lf = v - __uint_as_float(h);
    uint32_t l = __float_as_uint(lf) & 0xFFFFE000u;
    return make_uint2(h, l);
}

#if TC_ENABLED
__device__ __forceinline__ void mbar_init(uint32_t a, uint32_t c) {
    asm volatile("mbarrier.init.shared.b64 [%0], %1;" :: "r"(a), "r"(c) : "memory");
}
__device__ __forceinline__ void mbar_arrive(uint32_t a) {
    asm volatile("mbarrier.arrive.shared.b64 _, [%0];" :: "r"(a) : "memory");
}
__device__ __forceinline__ void mbar_wait(uint32_t a, uint32_t ph) {
    asm volatile(
        "{\n\t.reg .pred P;\n"
        "W_%=:\n\t"
        "mbarrier.try_wait.parity.acquire.cta.shared::cta.b64 P, [%0], %1, 0x989680;\n\t"
        "@P bra.uni D_%=;\n\t"
        "bra.uni W_%=;\n"
        "D_%=:\n\t}"
        :: "r"(a), "r"(ph) : "memory");
}
__device__ __forceinline__ void tmem_alloc(uint32_t dst, uint32_t n) {
    asm volatile("tcgen05.alloc.cta_group::1.sync.aligned.shared::cta.b32 [%0], %1;"
                 :: "r"(dst), "r"(n) : "memory");
}
__device__ __forceinline__ void tmem_dealloc(uint32_t t, uint32_t n) {
    asm volatile("tcgen05.relinquish_alloc_permit.cta_group::1.sync.aligned;");
    asm volatile("tcgen05.dealloc.cta_group::1.sync.aligned.b32 %0, %1;" :: "r"(t), "r"(n));
}
__device__ __forceinline__ void mma_tf32(uint32_t d, uint64_t ad, uint64_t bd,
                                         uint32_t idesc, uint32_t en) {
    asm volatile(
        "{\n\t.reg .pred p;\n\tsetp.ne.u32 p, %4, 0;\n\t"
        "tcgen05.mma.cta_group::1.kind::tf32 [%0], %1, %2, %3, {%5,%5,%5,%5}, p;\n\t}"
        :: "r"(d), "l"(ad), "l"(bd), "r"(idesc), "r"(en), "r"(0u) : "memory");
}
__device__ __forceinline__ void mma_commit(uint32_t mbar) {
    asm volatile("tcgen05.commit.cta_group::1.mbarrier::arrive::one.shared::cluster.b64 [%0];"
                 :: "r"(mbar) : "memory");
}
#define TC_FENCE_AFTER()     asm volatile("tcgen05.fence::after_thread_sync;" ::: "memory")
#define TC_FENCE_BEFORE()    asm volatile("tcgen05.fence::before_thread_sync;" ::: "memory")
#define TMEM_WAIT_LD()       asm volatile("tcgen05.wait::ld.sync.aligned;" ::: "memory")
#define FENCE_ASYNC_SHARED() asm volatile("fence.proxy.async.shared::cta;" ::: "memory")

#define LDTM_X32(r, a) \
    asm volatile( \
        "tcgen05.ld.sync.aligned.32x32b.x32.b32 " \
        "{%0, %1, %2, %3, %4, %5, %6, %7, " \
        " %8, %9, %10, %11, %12, %13, %14, %15, " \
        " %16, %17, %18, %19, %20, %21, %22, %23, " \
        " %24, %25, %26, %27, %28, %29, %30, %31}, [%32];" \
        : "=r"((r)[0]),  "=r"((r)[1]),  "=r"((r)[2]),  "=r"((r)[3]), \
          "=r"((r)[4]),  "=r"((r)[5]),  "=r"((r)[6]),  "=r"((r)[7]), \
          "=r"((r)[8]),  "=r"((r)[9]),  "=r"((r)[10]), "=r"((r)[11]), \
          "=r"((r)[12]), "=r"((r)[13]), "=r"((r)[14]), "=r"((r)[15]), \
          "=r"((r)[16]), "=r"((r)[17]), "=r"((r)[18]), "=r"((r)[19]), \
          "=r"((r)[20]), "=r"((r)[21]), "=r"((r)[22]), "=r"((r)[23]), \
          "=r"((r)[24]), "=r"((r)[25]), "=r"((r)[26]), "=r"((r)[27]), \
          "=r"((r)[28]), "=r"((r)[29]), "=r"((r)[30]), "=r"((r)[31]) \
        : "r"(a))
#endif  // TC_ENABLED

// SW128 K-major SMEM descriptor base: LBO=1, SBO=64, layout=2, version=1
static constexpr unsigned long long DESC_BASE =
    (2ull << 61) | (1ull << 46) | (64ull << 32) | (1ull << 16);

// ---------------- prep kernels ----------------
// transpose + pad: g_xt[(b*768+c)*224 + p] = x[(b*196+p)*768 + c]
__global__ void xt_kernel(const float* __restrict__ x) {
    __shared__ float s[32][33];
    const int b = blockIdx.z, pt = blockIdx.y, ct = blockIdx.x;
    const int lane = threadIdx.x & 31, grp = threadIdx.x >> 5;
#pragma unroll
    for (int k = 0; k < 4; ++k) {
        int p = pt * 32 + grp + k * 8;
        float v = 0.f;
        if (p < 196) v = x[((long)(b * 196 + p)) * 768 + ct * 32 + lane];
        s[grp + k * 8][lane] = v;
    }
    __syncthreads();
#pragma unroll
    for (int k = 0; k < 4; ++k) {
        int c = grp + k * 8;
        g_xt[((long)(b * 768 + ct * 32 + c)) * 224 + pt * 32 + lane] = s[lane][c];
    }
}

// blocks [0,336): g_twp pad; [336,720): g_w2p pad; [720,768): g_twn (warp/row)
__global__ void pad_kernel(const float* __restrict__ tw, const float* __restrict__ w2) {
    int blk = blockIdx.x;
    if (blk < 336) {
        int i = blk * 256 + threadIdx.x;           // < 86016 = 384*224
        int r = i / 224, c = i - r * 224;
        g_twp[i] = (c < 196) ? tw[r * 196 + c] : 0.f;
    } else if (blk < 720) {
        int i = (blk - 336) * 256 + threadIdx.x;   // < 98304 = 256*384
        int r = i / 384, c = i - r * 384;
        g_w2p[i] = (r < 196) ? w2[r * 384 + c] : 0.f;
    } else {
        int row = (blk - 720) * 8 + (threadIdx.x >> 5);   // < 384
        int lane = threadIdx.x & 31;
        const float* p = tw + (long)row * 196;
        float s = 0.f;
        for (int k = lane; k < 196; k += 32) { float v = p[k]; s = fmaf(v, v, s); }
#pragma unroll
        for (int o = 16; o; o >>= 1) s += __shfl_xor_sync(0xffffffffu, s, o);
        if (lane == 0) g_twn[row] = s;
    }
}

// g_xn1 from g_xt rows (contiguous, pad zeros included)
__global__ void xnorm_kernel() {
    int row = blockIdx.x * 8 + (threadIdx.x >> 5);   // 6144 blocks -> 49152 rows
    int lane = threadIdx.x & 31;
    const float* p = g_xt + (long)row * 224;
    float s = 0.f;
    for (int k = lane; k < 224; k += 32) { float v = p[k]; s = fmaf(v, v, s); }
#pragma unroll
    for (int o = 16; o; o >>= 1) s += __shfl_xor_sync(0xffffffffu, s, o);
    if (lane == 0) g_xn1[row] = s;
}

// fused: rows [0,3072) -> g_cwn from cw; rows [3072,15616) -> g_xn2 from g_X2
__global__ void normcx_kernel(const float* __restrict__ cw) {
    int row = blockIdx.x * 8 + (threadIdx.x >> 5);   // 1952 blocks -> 15616 rows
    int lane = threadIdx.x & 31;
    const float* p = (row < 3072) ? (cw + (long)row * 768)
                                  : (g_X2 + (long)(row - 3072) * 768);
    float s = 0.f;
    for (int k = lane; k < 768; k += 32) { float v = p[k]; s = fmaf(v, v, s); }
#pragma unroll
    for (int o = 16; o; o >>= 1) s += __shfl_xor_sync(0xffffffffu, s, o);
    if (lane == 0) {
        if (row < 3072) g_cwn[row] = s; else g_xn2[row - 3072] = s;
    }
}

// ---------------------------------------------------------------------------
// Unified tcgen05 3xTF32 GEMM:  C[m,n] = sum_k A[m,k] * W[n,k]
// MODE 0: A=g_xt  K=224,  W=g_twp, NTILE=128, N=384;  epi = token YAT -> g_H1
// MODE 1: A=g_H1  K=384,  W=g_w2p, NTILE=256, N=196;  epi = residual+transpose -> g_X2
// MODE 2: A=g_X2  K=768,  W=cw,    NTILE=256, N=3072; epi = channel YAT -> g_H3
// MODE 3: A=g_H3  K=3072, W=w4,    NTILE=256, N=768;  epi = residual -> out
// Stage: [Ah 16K][Al 16K][Bh NTILE*128][Bl NTILE*128], 2 stages, K-chunk 32.
// ---------------------------------------------------------------------------
template<int MODE>
__global__ __launch_bounds__(256, 1) void gemm_tc(
    const float* __restrict__ Wext,
    const float* __restrict__ bias,
    const float* __restrict__ alpha,
    const float* __restrict__ resx,
    float* __restrict__ outx)
{
    constexpr int K     = (MODE == 0) ? 224 : (MODE == 1) ? 384 : (MODE == 2) ? 768 : 3072;
    constexpr int NTILE = (MODE == 0) ? 128 : 256;
    constexpr int NB    = NTILE / 32;       // B row-groups per chunk
    constexpr int NCH   = K / 32;           // K chunks
    constexpr int SG    = 32768 + NTILE * 256;  // stage bytes
    const float* A = (MODE == 0) ? g_xt : (MODE == 1) ? g_H1 : (MODE == 2) ? g_X2 : g_H3;
    const float* W = (MODE == 0) ? g_twp : (MODE == 1) ? g_w2p : Wext;
    float* out = (MODE == 0) ? g_H1 : (MODE == 1) ? g_X2 : (MODE == 2) ? g_H3 : outx;

    extern __shared__ char smem[];

#if TC_ENABLED
    constexpr uint32_t IDESC =
        (1u << 4) | (2u << 7) | (2u << 10) | ((NTILE / 8) << 17) | (8u << 24);

    const uint32_t sb = smem_u32(smem);
    const uint32_t FULL0 = sb + 16, EMPTY0 = sb + 32, DONE = sb + 48;
    const uint32_t stage0 = (sb + 5120 + 1023) & ~1023u;
    char* stage_ptr0 = smem + (stage0 - sb);
    float* lutW = (float*)(smem + 1024);
    float* lutB = (float*)(smem + 2048);

    const int tid = threadIdx.x;
    const int wid = tid >> 5, lane = tid & 31;
    const int m0 = blockIdx.y * 128;
    const int n0 = blockIdx.x * NTILE;

    if (tid == 0) {
        mbar_init(FULL0, 256);  mbar_init(FULL0 + 8, 256);
        mbar_init(EMPTY0, 1);   mbar_init(EMPTY0 + 8, 1);
        mbar_init(DONE, 1);
    }
    if (wid == 0) tmem_alloc(sb, NTILE);
    if (tid < NTILE) {
        if constexpr (MODE == 0) { lutW[tid] = g_twn[n0 + tid]; lutB[tid] = bias[n0 + tid]; }
        if constexpr (MODE == 2) { lutW[tid] = g_cwn[n0 + tid]; lutB[tid] = bias[n0 + tid]; }
        if constexpr (MODE == 1) { lutB[tid] = (tid < 196) ? bias[tid] : 0.f; }
        if constexpr (MODE == 3) { lutB[tid] = bias[n0 + tid]; }
    }
    __syncthreads();
    uint32_t tmem;
    asm volatile("ld.shared.b32 %0, [%1];" : "=r"(tmem) : "r"(sb));

    // producer mapping: 8 threads per 128B row; swizzle XOR is constant per thread
    const int r8 = tid >> 3;
    const int c8 = (tid & 7) * 4;
    const uint32_t obase = (uint32_t)(r8 * 128) + (uint32_t)(((tid & 7) * 16) ^ ((r8 & 7) << 4));
    const float* Abase = A + (long)(m0 + r8) * K + c8;
    const float* Bbase = W + (long)(n0 + r8) * K + c8;

    float4 pf[4 + NB];
#pragma unroll
    for (int q = 0; q < 4; ++q)  pf[q]     = *(const float4*)(Abase + q * (32 * K));
#pragma unroll
    for (int q = 0; q < NB; ++q) pf[4 + q] = *(const float4*)(Bbase + q * (32 * K));

    for (int t = 0; t < NCH; ++t) {
        const int s = t & 1;
        if (t >= 2) mbar_wait(EMPTY0 + s * 8, ((t >> 1) - 1) & 1);
        char* st = stage_ptr0 + s * SG;
#pragma unroll
        for (int q = 0; q < 4; ++q) {           // A hi/lo
            uint2 sx = msplit(pf[q].x), sy = msplit(pf[q].y),
                  sz = msplit(pf[q].z), sw = msplit(pf[q].w);
            *(uint4*)(st + q * 4096 + obase)         = make_uint4(sx.x, sy.x, sz.x, sw.x);
            *(uint4*)(st + 16384 + q * 4096 + obase) = make_uint4(sx.y, sy.y, sz.y, sw.y);
        }
#pragma unroll
        for (int q = 0; q < NB; ++q) {          // B hi/lo
            uint2 sx = msplit(pf[4 + q].x), sy = msplit(pf[4 + q].y),
                  sz = msplit(pf[4 + q].z), sw = msplit(pf[4 + q].w);
            *(uint4*)(st + 32768 + q * 4096 + obase)              = make_uint4(sx.x, sy.x, sz.x, sw.x);
            *(uint4*)(st + 32768 + NTILE * 128 + q * 4096 + obase) = make_uint4(sx.y, sy.y, sz.y, sw.y);
        }
        FENCE_ASYNC_SHARED();
        mbar_arrive(FULL0 + s * 8);

        // prefetch next chunk's operands while MMAs of this chunk run
        if (t + 1 < NCH) {
            const int kc = (t + 1) * 32;
#pragma unroll
            for (int q = 0; q < 4; ++q)  pf[q]     = *(const float4*)(Abase + q * (32 * K) + kc);
#pragma unroll
            for (int q = 0; q < NB; ++q) pf[4 + q] = *(const float4*)(Bbase + q * (32 * K) + kc);
        }

        if (tid == 0) {
            mbar_wait(FULL0 + s * 8, (t >> 1) & 1);
            const uint32_t sa = stage0 + s * SG;
            const uint64_t dah = DESC_BASE | ((uint64_t)(sa >> 4) & 0x3FFF);
            const uint64_t dal = DESC_BASE | ((uint64_t)((sa + 16384) >> 4) & 0x3FFF);
            const uint64_t dbh = DESC_BASE | ((uint64_t)((sa + 32768) >> 4) & 0x3FFF);
            const uint64_t dbl = DESC_BASE | ((uint64_t)((sa + 32768 + NTILE * 128) >> 4) & 0x3FFF);
#pragma unroll
            for (int ks = 0; ks < 4; ++ks) {
                const uint32_t en = (t > 0 || ks > 0) ? 1u : 0u;
                mma_tf32(tmem, dah + ks * 2, dbh + ks * 2, IDESC, en);
                mma_tf32(tmem, dah + ks * 2, dbl + ks * 2, IDESC, 1u);
                mma_tf32(tmem, dal + ks * 2, dbh + ks * 2, IDESC, 1u);
            }
            mma_commit(EMPTY0 + s * 8);
        }
    }
    if (tid == 0) mma_commit(DONE);
    mbar_wait(DONE, 0);
    TC_FENCE_AFTER();

    // ---- epilogue: half-warpgroups split columns; warps map TMEM subpartitions ----
    constexpr int NCS = NTILE / 64;                   // 32-col batches per warp
    const int cb0 = (wid >> 2) * (NTILE / 2);
    const long m = m0 + (wid & 3) * 32 + lane;

    float sc = 0.f, xv = 0.f;
    if constexpr (MODE == 0) { sc = powf(sqrtf(384.f / logf(385.f)), alpha[0]);  xv = g_xn1[m]; }
    if constexpr (MODE == 2) { sc = powf(sqrtf(3072.f / logf(3073.f)), alpha[0]); xv = g_xn2[m]; }

#pragma unroll
    for (int cs = 0; cs < NCS; ++cs) {
        uint32_t r[32];
        LDTM_X32(r, tmem + cb0 + cs * 32);
        TMEM_WAIT_LD();
        const int nb = cb0 + cs * 32;

        if constexpr (MODE == 0 || MODE == 2) {
            constexpr int LD = (MODE == 0) ? 384 : 3072;
            float* orow = out + m * LD + n0 + nb;
#pragma unroll
            for (int q = 0; q < 8; ++q) {
                float4 o;
                float* op = (float*)&o;
#pragma unroll
                for (int jj = 0; jj < 4; ++jj) {
                    const int j = q * 4 + jj;
                    const float d  = __uint_as_float(r[j]);
                    const float dt = d + lutB[nb + j];
                    const float ds = lutW[nb + j] + xv - 2.0f * d + EPSV;
                    op[jj] = sc * dt * dt / ds;
                }
                *(float4*)(orow + q * 4) = o;
            }
        } else if constexpr (MODE == 1) {
            // transpose write: m=(b,c), col=p; X2[(b,p,c)] = x + acc + b2[p]
            const long bq = m / 768;
            const int cq = (int)(m - bq * 768);
#pragma unroll
            for (int j = 0; j < 32; ++j) {
                const int p = nb + j;
                if (p < 196) {
                    const long o = (bq * 196 + p) * 768 + cq;
                    out[o] = resx[o] + __uint_as_float(r[j]) + lutB[p];
                }
            }
        } else {
            const float* rrow = g_X2 + m * 768 + n0 + nb;
            float* orow = out + m * 768 + n0 + nb;
#pragma unroll
            for (int q = 0; q < 8; ++q) {
                const float4 rv = *(const float4*)(rrow + q * 4);
                float4 o;
                o.x = rv.x + __uint_as_float(r[q * 4 + 0]) + lutB[nb + q * 4 + 0];
                o.y = rv.y + __uint_as_float(r[q * 4 + 1]) + lutB[nb + q * 4 + 1];
                o.z = rv.z + __uint_as_float(r[q * 4 + 2]) + lutB[nb + q * 4 + 2];
                o.w = rv.w + __uint_as_float(r[q * 4 + 3]) + lutB[nb + q * 4 + 3];
                *(float4*)(orow + q * 4) = o;
            }
        }
    }
    TC_FENCE_BEFORE();
    __syncthreads();
    if (wid == 0) tmem_dealloc(tmem, NTILE);

#else   // ------- naive fallback: compiles on plain sm_103, never selected on GB300 -------
    const int tid = threadIdx.x;
    const int m0 = blockIdx.y * 128, n0 = blockIdx.x * NTILE;
    for (int e = tid; e < 128 * NTILE; e += 256) {
        const int i = e / NTILE, j = e - i * NTILE;
        const long m = m0 + i;
        const int n = n0 + j;
        float d = 0.f;
        for (int k = 0; k < K; ++k) d = fmaf(A[m * K + k], W[(long)n * K + k], d);
        if constexpr (MODE == 0 || MODE == 2) {
            constexpr float NF = (MODE == 0) ? 384.f : 3072.f;
            const float scf = powf(sqrtf(NF / logf(NF + 1.f)), alpha[0]);
            const float xvf = (MODE == 0) ? g_xn1[m] : g_xn2[m];
            const float wnf = (MODE == 0) ? g_twn[n] : g_cwn[n];
            const float dt = d + bias[n];
            out[m * ((MODE == 0) ? 384 : 3072) + n] = scf * dt * dt / (wnf + xvf - 2.f * d + EPSV);
        } else if constexpr (MODE == 1) {
            if (n < 196) {
                const long bq = m / 768, cq = m % 768;
                const long o = (bq * 196 + n) * 768 + cq;
                out[o] = resx[o] + d + bias[n];
            }
        } else {
            const long o = m * 768 + n;
            out[o] = g_X2[o] + d + bias[n];
        }
    }
#endif  // TC_ENABLED
}

// ---------------------------------------------------------------------------
#define SM_T0 (6144 + 2 * (32768 + 128 * 256))   // 137216
#define SM_TB (6144 + 2 * (32768 + 256 * 256))   // 202752

extern "C" void kernel_launch(void* const* d_in, const int* in_sizes, int n_in,
                              void* d_out, int out_size) {
    (void)in_sizes; (void)n_in; (void)out_size;
    const float* x  = (const float*)d_in[0];
    const float* tw = (const float*)d_in[1];
    const float* tb = (const float*)d_in[2];
    const float* ta = (const float*)d_in[3];
    const float* w2 = (const float*)d_in[4];
    const float* b2 = (const float*)d_in[5];
    const float* cw = (const float*)d_in[6];
    const float* cb = (const float*)d_in[7];
    const float* ca = (const float*)d_in[8];
    const float* w4 = (const float*)d_in[9];
    const float* b4 = (const float*)d_in[10];
    float* outp = (float*)d_out;

    static int smem_set = 0;
    if (!smem_set) {
        cudaFuncSetAttribute(gemm_tc<0>, cudaFuncAttributeMaxDynamicSharedMemorySize, SM_T0);
        cudaFuncSetAttribute(gemm_tc<1>, cudaFuncAttributeMaxDynamicSharedMemorySize, SM_TB);
        cudaFuncSetAttribute(gemm_tc<2>, cudaFuncAttributeMaxDynamicSharedMemorySize, SM_TB);
        cudaFuncSetAttribute(gemm_tc<3>, cudaFuncAttributeMaxDynamicSharedMemorySize, SM_TB);
        smem_set = 1;
    }

    // prep: transpose/pads/norms
    xt_kernel<<<dim3(24, 7, 64), 256>>>(x);                 // g_xt
    pad_kernel<<<768, 256>>>(tw, w2);                       // g_twp, g_w2p, g_twn
    xnorm_kernel<<<6144, 256>>>();                          // g_xn1

    // token mixing (tcgen05)
    gemm_tc<0><<<dim3(3, 384), 256, SM_T0>>>(nullptr, tb, ta, nullptr, nullptr);   // -> g_H1
    gemm_tc<1><<<dim3(1, 384), 256, SM_TB>>>(nullptr, b2, nullptr, x, nullptr);    // -> g_X2

    // channel mixing (tcgen05)
    normcx_kernel<<<1952, 256>>>(cw);                                              // g_cwn, g_xn2
    gemm_tc<2><<<dim3(12, 98), 256, SM_TB>>>(cw, cb, ca, nullptr, nullptr);        // -> g_H3
    gemm_tc<3><<<dim3(3, 98), 256, SM_TB>>>(w4, b4, nullptr, nullptr, outp);       // -> out
}